// round 3
// baseline (speedup 1.0000x reference)
#include <cuda_runtime.h>

// CollaborativeRNN (GRU-like): B=32, T=256, H=1024, V=10001
// out = [h_final (B*H) | logits (B*T*V)]  (float32)

#define BB 32
#define TT 256
#define HH 1024
#define H2 2048
#define VV 10001

// Scratch (device globals; no allocations allowed)
__device__ float g_h[HH * BB];        // h transposed: g_h[k*BB + b]
__device__ float g_rh[HH * BB];       // (r * h) transposed
__device__ float g_u[HH * BB];        // u gate transposed
__device__ float g_states[BB * TT * HH]; // states row-major [B*T, H]
__device__ int   g_items[BB * TT];    // canonicalized int32 item ids
__device__ int   g_nzodd;             // dtype-detect flag

typedef unsigned long long u64;

__device__ __forceinline__ u64 fma2(u64 a, u64 b, u64 c) {
    u64 d;
    asm("fma.rn.f32x2 %0, %1, %2, %3;" : "=l"(d) : "l"(a), "l"(b), "l"(c));
    return d;
}
__device__ __forceinline__ u64 pack2(float x, float y) {
    u64 d;
    asm("mov.b64 %0, {%1, %2};" : "=l"(d) : "f"(x), "f"(y));
    return d;
}
__device__ __forceinline__ void unpack2(u64 v, float &x, float &y) {
    asm("mov.b64 {%0, %1}, %2;" : "=f"(x), "=f"(y) : "l"(v));
}

// ---------------------------------------------------------------------------
// init: h0 [B,H] -> g_h transposed [H,B]; reset dtype-detect flag
__global__ void k_init(const float* __restrict__ h0) {
    int i = blockIdx.x * blockDim.x + threadIdx.x;
    if (i == 0) g_nzodd = 0;
    if (i < BB * HH) {
        int b = i / HH, k = i % HH;
        g_h[k * BB + b] = h0[i];
    }
}

// Detect items dtype: if the buffer is int64 (values in [0,10001)), every odd
// 32-bit word among the first 8192 words is 0. For int32 data those words are
// random item ids. Only touches the first 8192 words (in-bounds either way).
__global__ void k_detect(const int* __restrict__ w) {
    int i = blockIdx.x * blockDim.x + threadIdx.x;   // 0..4095
    if (i < (BB * TT) / 2) {
        if (w[2 * i + 1] != 0) atomicOr(&g_nzodd, 1);
    }
}

// Canonicalize items into int32 g_items[8192].
__global__ void k_convert(const int* __restrict__ w) {
    int i = blockIdx.x * blockDim.x + threadIdx.x;   // 0..8191
    if (i < BB * TT) {
        g_items[i] = g_nzodd ? w[i] : w[2 * i];      // int32 : int64 low word
    }
}

// ---------------------------------------------------------------------------
// Phase A (per step): ru = sigmoid(E_ru[item] + h@W_ru + b_ru)
//   j <  H : g_rh[j][b] = r * h[j][b]
//   j >= H : g_u[j-H][b] = u
// Grid: 2048/16 = 128 blocks, 128 threads (16 cols x 8 row-groups, 4 rows/thread)
__global__ __launch_bounds__(128) void k_stepA(
    const float* __restrict__ Eru,
    const float* __restrict__ Wru,
    const float* __restrict__ bru,
    int t)
{
    const int lane = threadIdx.x & 15;
    const int rg   = threadIdx.x >> 4;        // 0..7
    const int col  = blockIdx.x * 16 + lane;  // 0..2047
    const int b0   = rg * 4;

    __shared__ float hs[64][BB];

    const float bias = bru[col];
    float a[4];
#pragma unroll
    for (int r = 0; r < 4; r++) {
        int it = g_items[(b0 + r) * TT + t];
        a[r] = Eru[it * H2 + col] + bias;
    }
    u64 acc0 = pack2(a[0], a[1]);
    u64 acc1 = pack2(a[2], a[3]);

    for (int kc = 0; kc < HH; kc += 64) {
        __syncthreads();
#pragma unroll
        for (int i = 0; i < 16; i++) {
            int idx = threadIdx.x + i * 128;
            ((float*)hs)[idx] = g_h[kc * BB + idx];
        }
        __syncthreads();
#pragma unroll
        for (int k = 0; k < 64; k++) {
            float w = Wru[(kc + k) * H2 + col];
            u64 ww = pack2(w, w);
            ulonglong2 hv = *reinterpret_cast<const ulonglong2*>(&hs[k][b0]);
            acc0 = fma2(hv.x, ww, acc0);
            acc1 = fma2(hv.y, ww, acc1);
        }
    }

    float p[4];
    unpack2(acc0, p[0], p[1]);
    unpack2(acc1, p[2], p[3]);
#pragma unroll
    for (int r = 0; r < 4; r++)
        p[r] = 1.0f / (1.0f + expf(-p[r]));

    if (col < HH) {
        float4 hv = *reinterpret_cast<const float4*>(&g_h[col * BB + b0]);
        float4 o;
        o.x = p[0] * hv.x; o.y = p[1] * hv.y; o.z = p[2] * hv.z; o.w = p[3] * hv.w;
        *reinterpret_cast<float4*>(&g_rh[col * BB + b0]) = o;
    } else {
        float4 o; o.x = p[0]; o.y = p[1]; o.z = p[2]; o.w = p[3];
        *reinterpret_cast<float4*>(&g_u[(col - HH) * BB + b0]) = o;
    }
}

// ---------------------------------------------------------------------------
// Phase B (per step): c = tanh(E_c[item] + rh@W_c + b_c); h = u*h + (1-u)*c
// Grid: 1024/16 = 64 blocks, 128 threads
__global__ __launch_bounds__(128) void k_stepB(
    const float* __restrict__ Ec,
    const float* __restrict__ Wc,
    const float* __restrict__ bc,
    int t)
{
    const int lane = threadIdx.x & 15;
    const int rg   = threadIdx.x >> 4;
    const int col  = blockIdx.x * 16 + lane;  // 0..1023
    const int b0   = rg * 4;

    __shared__ float hs[64][BB];

    const float bias = bc[col];
    float a[4];
#pragma unroll
    for (int r = 0; r < 4; r++) {
        int it = g_items[(b0 + r) * TT + t];
        a[r] = Ec[it * HH + col] + bias;
    }
    u64 acc0 = pack2(a[0], a[1]);
    u64 acc1 = pack2(a[2], a[3]);

    for (int kc = 0; kc < HH; kc += 64) {
        __syncthreads();
#pragma unroll
        for (int i = 0; i < 16; i++) {
            int idx = threadIdx.x + i * 128;
            ((float*)hs)[idx] = g_rh[kc * BB + idx];
        }
        __syncthreads();
#pragma unroll
        for (int k = 0; k < 64; k++) {
            float w = Wc[(kc + k) * HH + col];
            u64 ww = pack2(w, w);
            ulonglong2 hv = *reinterpret_cast<const ulonglong2*>(&hs[k][b0]);
            acc0 = fma2(hv.x, ww, acc0);
            acc1 = fma2(hv.y, ww, acc1);
        }
    }

    float p[4];
    unpack2(acc0, p[0], p[1]);
    unpack2(acc1, p[2], p[3]);
#pragma unroll
    for (int r = 0; r < 4; r++)
        p[r] = tanhf(p[r]);

    float4 u4 = *reinterpret_cast<const float4*>(&g_u[col * BB + b0]);
    float4 hp = *reinterpret_cast<const float4*>(&g_h[col * BB + b0]);
    float4 hn;
    hn.x = u4.x * hp.x + (1.0f - u4.x) * p[0];
    hn.y = u4.y * hp.y + (1.0f - u4.y) * p[1];
    hn.z = u4.z * hp.z + (1.0f - u4.z) * p[2];
    hn.w = u4.w * hp.w + (1.0f - u4.w) * p[3];
    *reinterpret_cast<float4*>(&g_h[col * BB + b0]) = hn;

    float hnv[4] = {hn.x, hn.y, hn.z, hn.w};
#pragma unroll
    for (int r = 0; r < 4; r++)
        g_states[((b0 + r) * TT + t) * HH + col] = hnv[r];
}

// ---------------------------------------------------------------------------
// Output GEMM: C[8192, V] = states[8192, H] @ W_out[H, V]
// 64x64 block tile, 256 threads, 4x4 micro-tile (f32x2 packed FMA), k-chunk 16.
__global__ __launch_bounds__(256) void k_gemm(
    const float* __restrict__ Wo, float* __restrict__ C)
{
    const int tx = threadIdx.x & 15;   // n micro index
    const int ty = threadIdx.x >> 4;   // m micro index
    const int mt = blockIdx.x * 64;
    const int nt = blockIdx.y * 64;

    __shared__ float As[16][64];
    __shared__ float Bs[16][64];

    u64 acc[4][2];
#pragma unroll
    for (int i = 0; i < 4; i++) { acc[i][0] = 0ull; acc[i][1] = 0ull; }

    const int am = threadIdx.x >> 2;        // 0..63 (m within tile)
    const int ak = (threadIdx.x & 3) * 4;   // 0,4,8,12 (k within chunk)

    for (int k0 = 0; k0 < HH; k0 += 16) {
        float4 av = *reinterpret_cast<const float4*>(
            &g_states[(mt + am) * HH + k0 + ak]);
        float bv[4];
#pragma unroll
        for (int j = 0; j < 4; j++) {
            int idx = threadIdx.x + j * 256;
            int bk = idx >> 6, bn = idx & 63;
            int ncol = nt + bn;
            bv[j] = (ncol < VV) ? Wo[(k0 + bk) * VV + ncol] : 0.0f;
        }
        __syncthreads();
        As[ak + 0][am] = av.x;
        As[ak + 1][am] = av.y;
        As[ak + 2][am] = av.z;
        As[ak + 3][am] = av.w;
#pragma unroll
        for (int j = 0; j < 4; j++) {
            int idx = threadIdx.x + j * 256;
            Bs[idx >> 6][idx & 63] = bv[j];
        }
        __syncthreads();
#pragma unroll
        for (int k = 0; k < 16; k++) {
            float4 a4 = *reinterpret_cast<const float4*>(&As[k][ty * 4]);
            u64 b01 = *reinterpret_cast<const u64*>(&Bs[k][tx * 4]);
            u64 b23 = *reinterpret_cast<const u64*>(&Bs[k][tx * 4 + 2]);
            u64 aa;
            aa = pack2(a4.x, a4.x);
            acc[0][0] = fma2(aa, b01, acc[0][0]);
            acc[0][1] = fma2(aa, b23, acc[0][1]);
            aa = pack2(a4.y, a4.y);
            acc[1][0] = fma2(aa, b01, acc[1][0]);
            acc[1][1] = fma2(aa, b23, acc[1][1]);
            aa = pack2(a4.z, a4.z);
            acc[2][0] = fma2(aa, b01, acc[2][0]);
            acc[2][1] = fma2(aa, b23, acc[2][1]);
            aa = pack2(a4.w, a4.w);
            acc[3][0] = fma2(aa, b01, acc[3][0]);
            acc[3][1] = fma2(aa, b23, acc[3][1]);
        }
    }

    // Epilogue
#pragma unroll
    for (int i = 0; i < 4; i++) {
        int m = mt + ty * 4 + i;
        float c0, c1, c2, c3;
        unpack2(acc[i][0], c0, c1);
        unpack2(acc[i][1], c2, c3);
        int n = nt + tx * 4;
        float* row = &C[m * VV + n];
        if (n + 3 < VV) {
            row[0] = c0; row[1] = c1; row[2] = c2; row[3] = c3;
        } else {
            if (n     < VV) row[0] = c0;
            if (n + 1 < VV) row[1] = c1;
            if (n + 2 < VV) row[2] = c2;
            if (n + 3 < VV) row[3] = c3;
        }
    }
}

// ---------------------------------------------------------------------------
// h_final: g_h [H,B] -> out [B,H]
__global__ void k_hfinal(float* __restrict__ out) {
    int i = blockIdx.x * blockDim.x + threadIdx.x;
    if (i < BB * HH) {
        int b = i / HH, k = i % HH;
        out[i] = g_h[k * BB + b];
    }
}

// ---------------------------------------------------------------------------
extern "C" void kernel_launch(void* const* d_in, const int* in_sizes, int n_in,
                              void* d_out, int out_size)
{
    const int*   items_raw = (const int*)d_in[0];   // int32 or int64 (detected)
    const float* h0   = (const float*)d_in[1];
    const float* E_ru = (const float*)d_in[2];
    const float* W_ru = (const float*)d_in[3];
    const float* b_ru = (const float*)d_in[4];
    const float* E_c  = (const float*)d_in[5];
    const float* W_c  = (const float*)d_in[6];
    const float* b_c  = (const float*)d_in[7];
    const float* W_out = (const float*)d_in[8];

    float* out = (float*)d_out;
    float* logits = out + BB * HH;

    k_init<<<(BB * HH + 255) / 256, 256>>>(h0);
    k_detect<<<(BB * TT / 2 + 255) / 256, 256>>>(items_raw);
    k_convert<<<(BB * TT + 255) / 256, 256>>>(items_raw);

    for (int t = 0; t < TT; t++) {
        k_stepA<<<H2 / 16, 128>>>(E_ru, W_ru, b_ru, t);
        k_stepB<<<HH / 16, 128>>>(E_c, W_c, b_c, t);
    }

    dim3 ggrid((BB * TT) / 64, (VV + 63) / 64);
    k_gemm<<<ggrid, 256>>>(W_out, logits);

    k_hfinal<<<(BB * HH + 255) / 256, 256>>>(out);
}

// round 5
// speedup vs baseline: 1.1745x; 1.1745x over previous
#include <cuda_runtime.h>

// CollaborativeRNN (GRU-like): B=32, T=256, H=1024, V=10001
// out = [h_final (B*H) | logits (B*T*V)]  (float32)

#define BB 32
#define TT 256
#define HH 1024
#define H2 2048
#define VV 10001

typedef unsigned long long u64;

// Scratch (device globals; no allocations allowed)
__device__ float g_h[HH * BB];            // h transposed: g_h[k*BB + b]
__device__ float g_rh[HH * BB];           // (r * h) transposed
__device__ float g_u[HH * BB];            // u gate transposed
__device__ float g_states[BB * TT * HH];  // states row-major [B*T, H]
__device__ int   g_items[BB * TT];        // canonicalized int32 item ids
__device__ int   g_nzodd;                 // dtype-detect flag
__device__ u64   g_WruP[1024 * 1024];     // W_ru col-pair interleaved [cp][k]
__device__ u64   g_WcP[512 * 1024];       // W_c  col-pair interleaved [cp][k]

__device__ __forceinline__ u64 fma2(u64 a, u64 b, u64 c) {
    u64 d;
    asm("fma.rn.f32x2 %0, %1, %2, %3;" : "=l"(d) : "l"(a), "l"(b), "l"(c));
    return d;
}
__device__ __forceinline__ u64 pack2(float x, float y) {
    u64 d;
    asm("mov.b64 %0, {%1, %2};" : "=l"(d) : "f"(x), "f"(y));
    return d;
}
__device__ __forceinline__ void unpack2(u64 v, float &x, float &y) {
    asm("mov.b64 {%0, %1}, %2;" : "=f"(x), "=f"(y) : "l"(v));
}

// ---------------------------------------------------------------------------
// init: h0 [B,H] -> g_h transposed [H,B]; reset dtype-detect flag
__global__ void k_init(const float* __restrict__ h0) {
    int i = blockIdx.x * blockDim.x + threadIdx.x;
    if (i == 0) g_nzodd = 0;
    if (i < BB * HH) {
        int b = i / HH, k = i % HH;
        g_h[k * BB + b] = h0[i];
    }
}

// Detect items dtype (int64 -> odd 32-bit words all zero for ids < 10001).
__global__ void k_detect(const int* __restrict__ w) {
    int i = blockIdx.x * blockDim.x + threadIdx.x;
    if (i < (BB * TT) / 2) {
        if (w[2 * i + 1] != 0) atomicOr(&g_nzodd, 1);
    }
}
__global__ void k_convert(const int* __restrict__ w) {
    int i = blockIdx.x * blockDim.x + threadIdx.x;
    if (i < BB * TT) g_items[i] = g_nzodd ? w[i] : w[2 * i];
}

// ---------------------------------------------------------------------------
// Weight interleave: W[k][2cp],W[k][2cp+1] -> WP[cp*1024 + k]  (u64 pair)
__global__ void k_prepRu(const float* __restrict__ W) {
    int i = blockIdx.x * blockDim.x + threadIdx.x;     // 0 .. 1M-1
    int k = i >> 10, cp = i & 1023;
    float2 v = *reinterpret_cast<const float2*>(&W[k * H2 + 2 * cp]);
    g_WruP[cp * 1024 + k] = pack2(v.x, v.y);
}
__global__ void k_prepC(const float* __restrict__ W) {
    int i = blockIdx.x * blockDim.x + threadIdx.x;     // 0 .. 512K-1
    int k = i >> 9, cp = i & 511;
    float2 v = *reinterpret_cast<const float2*>(&W[k * HH + 2 * cp]);
    g_WcP[cp * 1024 + k] = pack2(v.x, v.y);
}

// ---------------------------------------------------------------------------
// Phase A: ru = sigmoid(E_ru[item] + h@W_ru + b_ru)
// Grid 256 blocks x 128 threads. Warp = one col-pair, full K.
// smem stages h in duplicated (h,h) u64 form, 128-k chunks.
__global__ __launch_bounds__(128) void k_stepA(
    const float* __restrict__ Eru,
    const float* __restrict__ bru,
    int t)
{
    const int lane = threadIdx.x & 31;
    const int w    = threadIdx.x >> 5;
    const int cp   = blockIdx.x * 4 + w;     // 0..1023
    const int col0 = 2 * cp;

    __shared__ u64 hs[128 * BB];             // 32 KB, (h,h) pairs [k][b]

    const int it = g_items[lane * TT + t];
    float2 e = *reinterpret_cast<const float2*>(&Eru[it * H2 + col0]);
    float2 bb = *reinterpret_cast<const float2*>(&bru[col0]);
    u64 acc = pack2(e.x + bb.x, e.y + bb.y);

    for (int kc = 0; kc < HH; kc += 128) {
        __syncthreads();
        // stage + duplicate: 4096 floats = 1024 float4s, 8 per thread
#pragma unroll
        for (int j = 0; j < 8; j++) {
            int idx4 = threadIdx.x + j * 128;          // float4 index 0..1023
            float4 v = reinterpret_cast<const float4*>(g_h + kc * BB)[idx4];
            hs[idx4 * 4 + 0] = pack2(v.x, v.x);
            hs[idx4 * 4 + 1] = pack2(v.y, v.y);
            hs[idx4 * 4 + 2] = pack2(v.z, v.z);
            hs[idx4 * 4 + 3] = pack2(v.w, v.w);
        }
        __syncthreads();
        const u64* wp = &g_WruP[cp * 1024 + kc];
#pragma unroll 8
        for (int k = 0; k < 128; k += 2) {
            ulonglong2 wv = *reinterpret_cast<const ulonglong2*>(&wp[k]);
            acc = fma2(hs[k * BB + lane], wv.x, acc);
            acc = fma2(hs[(k + 1) * BB + lane], wv.y, acc);
        }
    }

    float p0, p1;
    unpack2(acc, p0, p1);
    p0 = 1.0f / (1.0f + __expf(-p0));
    p1 = 1.0f / (1.0f + __expf(-p1));

    if (cp < 512) {  // r gates -> r*h
        g_rh[col0 * BB + lane]       = p0 * g_h[col0 * BB + lane];
        g_rh[(col0 + 1) * BB + lane] = p1 * g_h[(col0 + 1) * BB + lane];
    } else {         // u gates
        g_u[(col0 - HH) * BB + lane]     = p0;
        g_u[(col0 - HH + 1) * BB + lane] = p1;
    }
}

// ---------------------------------------------------------------------------
// Phase B: c = tanh(E_c[item] + rh@W_c + b_c); h = u*h + (1-u)*c
// Grid 128 blocks x 128 threads. Warp = one col-pair, full K.
__global__ __launch_bounds__(128) void k_stepB(
    const float* __restrict__ Ec,
    const float* __restrict__ bc,
    int t)
{
    const int lane = threadIdx.x & 31;
    const int w    = threadIdx.x >> 5;
    const int cp   = blockIdx.x * 4 + w;     // 0..511
    const int col0 = 2 * cp;

    __shared__ u64 hs[128 * BB];             // (rh,rh) pairs

    const int it = g_items[lane * TT + t];
    float2 e = *reinterpret_cast<const float2*>(&Ec[it * HH + col0]);
    float2 bb = *reinterpret_cast<const float2*>(&bc[col0]);
    u64 acc = pack2(e.x + bb.x, e.y + bb.y);

    for (int kc = 0; kc < HH; kc += 128) {
        __syncthreads();
#pragma unroll
        for (int j = 0; j < 8; j++) {
            int idx4 = threadIdx.x + j * 128;          // float4 index 0..1023
            float4 v = reinterpret_cast<const float4*>(g_rh + kc * BB)[idx4];
            hs[idx4 * 4 + 0] = pack2(v.x, v.x);
            hs[idx4 * 4 + 1] = pack2(v.y, v.y);
            hs[idx4 * 4 + 2] = pack2(v.z, v.z);
            hs[idx4 * 4 + 3] = pack2(v.w, v.w);
        }
        __syncthreads();
        const u64* wp = &g_WcP[cp * 1024 + kc];
#pragma unroll 8
        for (int k = 0; k < 128; k += 2) {
            ulonglong2 wv = *reinterpret_cast<const ulonglong2*>(&wp[k]);
            acc = fma2(hs[k * BB + lane], wv.x, acc);
            acc = fma2(hs[(k + 1) * BB + lane], wv.y, acc);
        }
    }

    float p0, p1;
    unpack2(acc, p0, p1);
    float c0 = tanhf(p0), c1 = tanhf(p1);

    float u0 = g_u[col0 * BB + lane];
    float u1 = g_u[(col0 + 1) * BB + lane];
    float h0 = g_h[col0 * BB + lane];
    float h1 = g_h[(col0 + 1) * BB + lane];
    float hn0 = u0 * h0 + (1.0f - u0) * c0;
    float hn1 = u1 * h1 + (1.0f - u1) * c1;
    g_h[col0 * BB + lane]       = hn0;
    g_h[(col0 + 1) * BB + lane] = hn1;
    *reinterpret_cast<float2*>(&g_states[(lane * TT + t) * HH + col0]) =
        make_float2(hn0, hn1);
}

// ---------------------------------------------------------------------------
// Output GEMM: C[8192, V] = states[8192, H] @ W_out[H, V]
// 64m x 128n tile, 256 threads, micro 4m x 8n. A staged duplicated (a,a).
__global__ __launch_bounds__(256) void k_gemm(
    const float* __restrict__ Wo, float* __restrict__ C)
{
    const int tx = threadIdx.x & 15;   // n group: n0 = tx*8
    const int ty = threadIdx.x >> 4;   // m group: m0 = ty*4
    const int mt = blockIdx.x * 64;
    const int nt = blockIdx.y * 128;

    __shared__ u64   Asd[16][64];      // 8 KB, (a,a) dup [k][m]
    __shared__ float Bs[16][128];      // 8 KB

    u64 acc[4][4];
#pragma unroll
    for (int i = 0; i < 4; i++)
#pragma unroll
        for (int j = 0; j < 4; j++) acc[i][j] = 0ull;

    const int am = threadIdx.x >> 2;        // 0..63
    const int ak = (threadIdx.x & 3) * 4;   // 0,4,8,12

    for (int k0 = 0; k0 < HH; k0 += 16) {
        float4 av = *reinterpret_cast<const float4*>(
            &g_states[(mt + am) * HH + k0 + ak]);
        float bv[8];
#pragma unroll
        for (int j = 0; j < 8; j++) {
            int idx = threadIdx.x + j * 256;      // 0..2047
            int bk = idx >> 7, bn = idx & 127;
            int ncol = nt + bn;
            bv[j] = (ncol < VV) ? Wo[(k0 + bk) * VV + ncol] : 0.0f;
        }
        __syncthreads();
        Asd[ak + 0][am] = pack2(av.x, av.x);
        Asd[ak + 1][am] = pack2(av.y, av.y);
        Asd[ak + 2][am] = pack2(av.z, av.z);
        Asd[ak + 3][am] = pack2(av.w, av.w);
#pragma unroll
        for (int j = 0; j < 8; j++) {
            int idx = threadIdx.x + j * 256;
            Bs[idx >> 7][idx & 127] = bv[j];
        }
        __syncthreads();
#pragma unroll
        for (int k = 0; k < 16; k++) {
            ulonglong2 a01 = *reinterpret_cast<const ulonglong2*>(&Asd[k][ty * 4]);
            ulonglong2 a23 = *reinterpret_cast<const ulonglong2*>(&Asd[k][ty * 4 + 2]);
            ulonglong2 b01 = *reinterpret_cast<const ulonglong2*>(&Bs[k][tx * 8]);
            ulonglong2 b23 = *reinterpret_cast<const ulonglong2*>(&Bs[k][tx * 8 + 4]);
            acc[0][0] = fma2(a01.x, b01.x, acc[0][0]);
            acc[0][1] = fma2(a01.x, b01.y, acc[0][1]);
            acc[0][2] = fma2(a01.x, b23.x, acc[0][2]);
            acc[0][3] = fma2(a01.x, b23.y, acc[0][3]);
            acc[1][0] = fma2(a01.y, b01.x, acc[1][0]);
            acc[1][1] = fma2(a01.y, b01.y, acc[1][1]);
            acc[1][2] = fma2(a01.y, b23.x, acc[1][2]);
            acc[1][3] = fma2(a01.y, b23.y, acc[1][3]);
            acc[2][0] = fma2(a23.x, b01.x, acc[2][0]);
            acc[2][1] = fma2(a23.x, b01.y, acc[2][1]);
            acc[2][2] = fma2(a23.x, b23.x, acc[2][2]);
            acc[2][3] = fma2(a23.x, b23.y, acc[2][3]);
            acc[3][0] = fma2(a23.y, b01.x, acc[3][0]);
            acc[3][1] = fma2(a23.y, b01.y, acc[3][1]);
            acc[3][2] = fma2(a23.y, b23.x, acc[3][2]);
            acc[3][3] = fma2(a23.y, b23.y, acc[3][3]);
        }
    }

    // Epilogue (scalar stores; V=10001 rows are 16B-misaligned)
#pragma unroll
    for (int i = 0; i < 4; i++) {
        int m = mt + ty * 4 + i;
        float* row = &C[m * VV];
#pragma unroll
        for (int j = 0; j < 4; j++) {
            float c0, c1;
            unpack2(acc[i][j], c0, c1);
            int n = nt + tx * 8 + j * 2;
            if (n < VV)     row[n]     = c0;
            if (n + 1 < VV) row[n + 1] = c1;
        }
    }
}

// ---------------------------------------------------------------------------
// h_final: g_h [H,B] -> out [B,H]
__global__ void k_hfinal(float* __restrict__ out) {
    int i = blockIdx.x * blockDim.x + threadIdx.x;
    if (i < BB * HH) {
        int b = i / HH, k = i % HH;
        out[i] = g_h[k * BB + b];
    }
}

// ---------------------------------------------------------------------------
extern "C" void kernel_launch(void* const* d_in, const int* in_sizes, int n_in,
                              void* d_out, int out_size)
{
    const int*   items_raw = (const int*)d_in[0];
    const float* h0   = (const float*)d_in[1];
    const float* E_ru = (const float*)d_in[2];
    const float* W_ru = (const float*)d_in[3];
    const float* b_ru = (const float*)d_in[4];
    const float* E_c  = (const float*)d_in[5];
    const float* W_c  = (const float*)d_in[6];
    const float* b_c  = (const float*)d_in[7];
    const float* W_out = (const float*)d_in[8];

    float* out = (float*)d_out;
    float* logits = out + BB * HH;

    k_init<<<(BB * HH + 255) / 256, 256>>>(h0);
    k_detect<<<(BB * TT / 2 + 255) / 256, 256>>>(items_raw);
    k_convert<<<(BB * TT + 255) / 256, 256>>>(items_raw);
    k_prepRu<<<(1024 * 1024) / 256, 256>>>(W_ru);
    k_prepC<<<(512 * 1024) / 256, 256>>>(W_c);

    for (int t = 0; t < TT; t++) {
        k_stepA<<<256, 128>>>(E_ru, b_ru, t);
        k_stepB<<<128, 128>>>(E_c, b_c, t);
    }

    dim3 ggrid((BB * TT) / 64, (VV + 127) / 128);
    k_gemm<<<ggrid, 256>>>(W_out, logits);

    k_hfinal<<<(BB * HH + 255) / 256, 256>>>(out);
}

// round 6
// speedup vs baseline: 1.7477x; 1.4880x over previous
#include <cuda_runtime.h>

// CollaborativeRNN (GRU-like): B=32, T=256, H=1024, V=10001
// out = [h_final (B*H) | logits (B*T*V)]  (float32)

#define BB 32
#define TT 256
#define HH 1024
#define H2 2048
#define VV 10001
#define NB 128    // persistent grid size (<=148 SMs, 1 block/SM)

typedef unsigned long long u64;

// Scratch (device globals; no allocations allowed)
__device__ float g_h[HH * BB];            // h transposed: g_h[k*BB + b]
__device__ float g_rh[HH * BB];           // (r * h) transposed
__device__ float g_u[HH * BB];            // u gate transposed
__device__ float g_states[BB * TT * HH];  // states row-major [B*T, H]
__device__ int   g_items[BB * TT];        // canonicalized int32 item ids
__device__ int   g_nzodd;                 // dtype-detect flag
__device__ int   g_count;                 // grid barrier counter
__device__ volatile int g_gen;            // grid barrier generation

__device__ __forceinline__ u64 fma2(u64 a, u64 b, u64 c) {
    u64 d;
    asm("fma.rn.f32x2 %0, %1, %2, %3;" : "=l"(d) : "l"(a), "l"(b), "l"(c));
    return d;
}
__device__ __forceinline__ u64 add2(u64 a, u64 b) {
    u64 d;
    asm("add.rn.f32x2 %0, %1, %2;" : "=l"(d) : "l"(a), "l"(b));
    return d;
}
__device__ __forceinline__ u64 pack2(float x, float y) {
    u64 d;
    asm("mov.b64 %0, {%1, %2};" : "=l"(d) : "f"(x), "f"(y));
    return d;
}
__device__ __forceinline__ void unpack2(u64 v, float &x, float &y) {
    asm("mov.b64 {%0, %1}, %2;" : "=f"(x), "=f"(y) : "l"(v));
}

// ---------------------------------------------------------------------------
__global__ void k_init(const float* __restrict__ h0) {
    int i = blockIdx.x * blockDim.x + threadIdx.x;
    if (i == 0) { g_nzodd = 0; g_count = 0; g_gen = 0; }
    if (i < BB * HH) {
        int b = i / HH, k = i % HH;
        g_h[k * BB + b] = h0[i];
    }
}

__global__ void k_detect(const int* __restrict__ w) {
    int i = blockIdx.x * blockDim.x + threadIdx.x;
    if (i < (BB * TT) / 2) {
        if (w[2 * i + 1] != 0) atomicOr(&g_nzodd, 1);
    }
}
__global__ void k_convert(const int* __restrict__ w) {
    int i = blockIdx.x * blockDim.x + threadIdx.x;
    if (i < BB * TT) g_items[i] = g_nzodd ? w[i] : w[2 * i];
}

// ---------------------------------------------------------------------------
// Grid barrier (all NB blocks resident; L2-based, release/acquire via fences)
__device__ __forceinline__ void gridbar() {
    __syncthreads();
    if (threadIdx.x == 0) {
        __threadfence();
        int gen = g_gen;
        if (atomicAdd(&g_count, 1) == NB - 1) {
            atomicExch(&g_count, 0);
            __threadfence();
            g_gen = gen + 1;
        } else {
            while (g_gen == gen) { }
            __threadfence();
        }
    }
    __syncthreads();
}

// ---------------------------------------------------------------------------
// Persistent recurrence kernel. 128 blocks x 256 threads.
// Block owns: 8 col-pairs of W_ru (cols blk*16..+15) and 4 col-pairs of W_c
// (cols blk*8..+7), resident in smem for all 256 steps.
// Dynamic smem layout:
//   Wa : 8192 u64  (64 KB)   [k][cpl0..7]  (w_col0,w_col1) pairs
//   Wb : 4096 u64  (32 KB)   [k][cpl0..3]
//   hs : 16384 f32 (64 KB)   staged h/rh chunk (512 k x 32 b)
//   red: 1024 u64  ( 8 KB)   cross-warp partial reduction
__global__ __launch_bounds__(256) void k_rnn(
    const float* __restrict__ Eru, const float* __restrict__ bru,
    const float* __restrict__ Ec,  const float* __restrict__ bc,
    const float* __restrict__ Wru, const float* __restrict__ Wc)
{
    extern __shared__ char smem[];
    u64*   Wa  = (u64*)smem;                     // 65536 B
    u64*   Wb  = (u64*)(smem + 65536);           // 32768 B
    float* hs  = (float*)(smem + 98304);         // 65536 B
    u64*   red = (u64*)(smem + 163840);          //  8192 B

    const int tid  = threadIdx.x;
    const int lane = tid & 31;
    const int wid  = tid >> 5;
    const int blk  = blockIdx.x;

    // One-time weight load into smem (packed col-pairs)
    for (int i = tid; i < 8192; i += 256) {
        int k = i >> 3, cpl = i & 7;
        float2 w = *reinterpret_cast<const float2*>(&Wru[k * H2 + blk * 16 + 2 * cpl]);
        Wa[k * 8 + cpl] = pack2(w.x, w.y);
    }
    for (int i = tid; i < 4096; i += 256) {
        int k = i >> 2, cpl = i & 3;
        float2 w = *reinterpret_cast<const float2*>(&Wc[k * HH + blk * 8 + 2 * cpl]);
        Wb[k * 4 + cpl] = pack2(w.x, w.y);
    }

    // Fixed per-thread roles
    const int cpA   = tid >> 5;                  // 0..7  (A output col-pair)
    const int col0A = blk * 16 + 2 * cpA;
    const float2 bA = *reinterpret_cast<const float2*>(&bru[col0A]);
    const int cpB   = tid >> 5;                  // 0..3 valid when tid<128
    const int col0B = blk * 8 + 2 * cpB;
    float2 bB = make_float2(0.f, 0.f);
    if (tid < 128) bB = *reinterpret_cast<const float2*>(&bc[col0B]);

    const int teamA = wid >> 2;                  // 0..1
    const int wkA   = wid & 3;                   // A k-range index

    __syncthreads();

    for (int t = 0; t < TT; t++) {
        // ================= Phase A: ru gates =================
        const int itA = g_items[lane * TT + t];
        const float2 eA = *reinterpret_cast<const float2*>(&Eru[itA * H2 + col0A]);

        u64 a0 = 0ull, a1 = 0ull, a2 = 0ull, a3 = 0ull;
#pragma unroll
        for (int c = 0; c < 2; c++) {
            __syncthreads();
            const float4* src = (const float4*)(g_h + c * 512 * BB);
#pragma unroll 4
            for (int j = 0; j < 16; j++)
                ((float4*)hs)[tid + j * 256] = __ldcg(&src[tid + j * 256]);
            __syncthreads();
            const int kbase = wkA * 128;
#pragma unroll 4
            for (int kl = kbase; kl < kbase + 128; kl++) {
                float hv = hs[kl * 32 + lane];
                u64 hd = pack2(hv, hv);
                ulonglong2 w01 = *reinterpret_cast<const ulonglong2*>(
                    &Wa[(c * 512 + kl) * 8 + teamA * 4]);
                ulonglong2 w23 = *reinterpret_cast<const ulonglong2*>(
                    &Wa[(c * 512 + kl) * 8 + teamA * 4 + 2]);
                a0 = fma2(hd, w01.x, a0);
                a1 = fma2(hd, w01.y, a1);
                a2 = fma2(hd, w23.x, a2);
                a3 = fma2(hd, w23.y, a3);
            }
        }
        // partials: red[wkA][cp=teamA*4+q][lane]
        red[(wkA * 8 + teamA * 4 + 0) * 32 + lane] = a0;
        red[(wkA * 8 + teamA * 4 + 1) * 32 + lane] = a1;
        red[(wkA * 8 + teamA * 4 + 2) * 32 + lane] = a2;
        red[(wkA * 8 + teamA * 4 + 3) * 32 + lane] = a3;
        __syncthreads();
        {
            int cp = tid >> 5;  // == cpA
            u64 s = red[(0 * 8 + cp) * 32 + lane];
            s = add2(s, red[(1 * 8 + cp) * 32 + lane]);
            s = add2(s, red[(2 * 8 + cp) * 32 + lane]);
            s = add2(s, red[(3 * 8 + cp) * 32 + lane]);
            float p0, p1;
            unpack2(s, p0, p1);
            p0 += eA.x + bA.x;
            p1 += eA.y + bA.y;
            p0 = 1.0f / (1.0f + __expf(-p0));
            p1 = 1.0f / (1.0f + __expf(-p1));
            int cpg = blk * 8 + cp;
            if (cpg < 512) {       // r gates -> r*h
                float h0 = __ldcg(&g_h[col0A * 32 + lane]);
                float h1 = __ldcg(&g_h[(col0A + 1) * 32 + lane]);
                __stcg(&g_rh[col0A * 32 + lane], p0 * h0);
                __stcg(&g_rh[(col0A + 1) * 32 + lane], p1 * h1);
            } else {               // u gates
                __stcg(&g_u[(col0A - HH) * 32 + lane], p0);
                __stcg(&g_u[(col0A - HH + 1) * 32 + lane], p1);
            }
        }
        gridbar();

        // ================= Phase B: candidate + h update =================
        float2 eB = make_float2(0.f, 0.f);
        if (tid < 128) {
            int itB = g_items[lane * TT + t];
            eB = *reinterpret_cast<const float2*>(&Ec[itB * HH + col0B]);
        }
        u64 b0 = 0ull, b1 = 0ull, b2 = 0ull, b3 = 0ull;
#pragma unroll
        for (int c = 0; c < 2; c++) {
            __syncthreads();
            const float4* src = (const float4*)(g_rh + c * 512 * BB);
#pragma unroll 4
            for (int j = 0; j < 16; j++)
                ((float4*)hs)[tid + j * 256] = __ldcg(&src[tid + j * 256]);
            __syncthreads();
            const int kbase = wid * 64;
#pragma unroll 4
            for (int kl = kbase; kl < kbase + 64; kl++) {
                float rv = hs[kl * 32 + lane];
                u64 rd = pack2(rv, rv);
                ulonglong2 w01 = *reinterpret_cast<const ulonglong2*>(
                    &Wb[(c * 512 + kl) * 4]);
                ulonglong2 w23 = *reinterpret_cast<const ulonglong2*>(
                    &Wb[(c * 512 + kl) * 4 + 2]);
                b0 = fma2(rd, w01.x, b0);
                b1 = fma2(rd, w01.y, b1);
                b2 = fma2(rd, w23.x, b2);
                b3 = fma2(rd, w23.y, b3);
            }
        }
        // partials: red[wid][cp 0..3][lane]
        red[(wid * 4 + 0) * 32 + lane] = b0;
        red[(wid * 4 + 1) * 32 + lane] = b1;
        red[(wid * 4 + 2) * 32 + lane] = b2;
        red[(wid * 4 + 3) * 32 + lane] = b3;
        __syncthreads();
        if (tid < 128) {
            int cp = tid >> 5;  // == cpB
            u64 s = red[(0 * 4 + cp) * 32 + lane];
#pragma unroll
            for (int w = 1; w < 8; w++)
                s = add2(s, red[(w * 4 + cp) * 32 + lane]);
            float c0, c1;
            unpack2(s, c0, c1);
            c0 = tanhf(c0 + eB.x + bB.x);
            c1 = tanhf(c1 + eB.y + bB.y);
            float u0 = __ldcg(&g_u[col0B * 32 + lane]);
            float u1 = __ldcg(&g_u[(col0B + 1) * 32 + lane]);
            float h0 = __ldcg(&g_h[col0B * 32 + lane]);
            float h1 = __ldcg(&g_h[(col0B + 1) * 32 + lane]);
            float hn0 = u0 * h0 + (1.0f - u0) * c0;
            float hn1 = u1 * h1 + (1.0f - u1) * c1;
            __stcg(&g_h[col0B * 32 + lane], hn0);
            __stcg(&g_h[(col0B + 1) * 32 + lane], hn1);
            __stcg(reinterpret_cast<float2*>(
                       &g_states[(lane * TT + t) * HH + col0B]),
                   make_float2(hn0, hn1));
        }
        gridbar();
    }
}

// ---------------------------------------------------------------------------
// Output GEMM: C[8192, V] = states[8192, H] @ W_out[H, V]
// 64m x 128n tile, 256 threads, micro 4m x 8n. A staged duplicated (a,a).
__global__ __launch_bounds__(256) void k_gemm(
    const float* __restrict__ Wo, float* __restrict__ C)
{
    const int tx = threadIdx.x & 15;   // n group: n0 = tx*8
    const int ty = threadIdx.x >> 4;   // m group: m0 = ty*4
    const int mt = blockIdx.x * 64;
    const int nt = blockIdx.y * 128;

    __shared__ u64   Asd[16][64];      // 8 KB, (a,a) dup [k][m]
    __shared__ float Bs[16][128];      // 8 KB

    u64 acc[4][4];
#pragma unroll
    for (int i = 0; i < 4; i++)
#pragma unroll
        for (int j = 0; j < 4; j++) acc[i][j] = 0ull;

    const int am = threadIdx.x >> 2;        // 0..63
    const int ak = (threadIdx.x & 3) * 4;   // 0,4,8,12

    for (int k0 = 0; k0 < HH; k0 += 16) {
        float4 av = *reinterpret_cast<const float4*>(
            &g_states[(mt + am) * HH + k0 + ak]);
        float bv[8];
#pragma unroll
        for (int j = 0; j < 8; j++) {
            int idx = threadIdx.x + j * 256;      // 0..2047
            int bk = idx >> 7, bn = idx & 127;
            int ncol = nt + bn;
            bv[j] = (ncol < VV) ? Wo[(k0 + bk) * VV + ncol] : 0.0f;
        }
        __syncthreads();
        Asd[ak + 0][am] = pack2(av.x, av.x);
        Asd[ak + 1][am] = pack2(av.y, av.y);
        Asd[ak + 2][am] = pack2(av.z, av.z);
        Asd[ak + 3][am] = pack2(av.w, av.w);
#pragma unroll
        for (int j = 0; j < 8; j++) {
            int idx = threadIdx.x + j * 256;
            Bs[idx >> 7][idx & 127] = bv[j];
        }
        __syncthreads();
#pragma unroll
        for (int k = 0; k < 16; k++) {
            ulonglong2 a01 = *reinterpret_cast<const ulonglong2*>(&Asd[k][ty * 4]);
            ulonglong2 a23 = *reinterpret_cast<const ulonglong2*>(&Asd[k][ty * 4 + 2]);
            ulonglong2 b01 = *reinterpret_cast<const ulonglong2*>(&Bs[k][tx * 8]);
            ulonglong2 b23 = *reinterpret_cast<const ulonglong2*>(&Bs[k][tx * 8 + 4]);
            acc[0][0] = fma2(a01.x, b01.x, acc[0][0]);
            acc[0][1] = fma2(a01.x, b01.y, acc[0][1]);
            acc[0][2] = fma2(a01.x, b23.x, acc[0][2]);
            acc[0][3] = fma2(a01.x, b23.y, acc[0][3]);
            acc[1][0] = fma2(a01.y, b01.x, acc[1][0]);
            acc[1][1] = fma2(a01.y, b01.y, acc[1][1]);
            acc[1][2] = fma2(a01.y, b23.x, acc[1][2]);
            acc[1][3] = fma2(a01.y, b23.y, acc[1][3]);
            acc[2][0] = fma2(a23.x, b01.x, acc[2][0]);
            acc[2][1] = fma2(a23.x, b01.y, acc[2][1]);
            acc[2][2] = fma2(a23.x, b23.x, acc[2][2]);
            acc[2][3] = fma2(a23.x, b23.y, acc[2][3]);
            acc[3][0] = fma2(a23.y, b01.x, acc[3][0]);
            acc[3][1] = fma2(a23.y, b01.y, acc[3][1]);
            acc[3][2] = fma2(a23.y, b23.x, acc[3][2]);
            acc[3][3] = fma2(a23.y, b23.y, acc[3][3]);
        }
    }

    // Epilogue (scalar stores; V=10001 rows are 16B-misaligned)
#pragma unroll
    for (int i = 0; i < 4; i++) {
        int m = mt + ty * 4 + i;
        float* row = &C[m * VV];
#pragma unroll
        for (int j = 0; j < 4; j++) {
            float c0, c1;
            unpack2(acc[i][j], c0, c1);
            int n = nt + tx * 8 + j * 2;
            if (n < VV)     row[n]     = c0;
            if (n + 1 < VV) row[n + 1] = c1;
        }
    }
}

// ---------------------------------------------------------------------------
// h_final: g_h [H,B] -> out [B,H]
__global__ void k_hfinal(float* __restrict__ out) {
    int i = blockIdx.x * blockDim.x + threadIdx.x;
    if (i < BB * HH) {
        int b = i / HH, k = i % HH;
        out[i] = g_h[k * BB + b];
    }
}

// ---------------------------------------------------------------------------
extern "C" void kernel_launch(void* const* d_in, const int* in_sizes, int n_in,
                              void* d_out, int out_size)
{
    const int*   items_raw = (const int*)d_in[0];
    const float* h0   = (const float*)d_in[1];
    const float* E_ru = (const float*)d_in[2];
    const float* W_ru = (const float*)d_in[3];
    const float* b_ru = (const float*)d_in[4];
    const float* E_c  = (const float*)d_in[5];
    const float* W_c  = (const float*)d_in[6];
    const float* b_c  = (const float*)d_in[7];
    const float* W_out = (const float*)d_in[8];

    float* out = (float*)d_out;
    float* logits = out + BB * HH;

    static bool attr_set = false;
    (void)attr_set;
    cudaFuncSetAttribute(k_rnn, cudaFuncAttributeMaxDynamicSharedMemorySize,
                         172032);

    k_init<<<(BB * HH + 255) / 256, 256>>>(h0);
    k_detect<<<(BB * TT / 2 + 255) / 256, 256>>>(items_raw);
    k_convert<<<(BB * TT + 255) / 256, 256>>>(items_raw);

    k_rnn<<<NB, 256, 172032>>>(E_ru, b_ru, E_c, b_c, W_ru, W_c);

    dim3 ggrid((BB * TT) / 64, (VV + 127) / 128);
    k_gemm<<<ggrid, 256>>>(W_out, logits);

    k_hfinal<<<(BB * HH + 255) / 256, 256>>>(out);
}

// round 7
// speedup vs baseline: 2.2925x; 1.3117x over previous
#include <cuda_runtime.h>

// CollaborativeRNN (GRU-like): B=32, T=256, H=1024, V=10001
// out = [h_final (B*H) | logits (B*T*V)]  (float32)

#define BB 32
#define TT 256
#define HH 1024
#define H2 2048
#define VV 10001
#define NB 128    // persistent grid size (<=148 SMs, 1 block/SM by smem)

typedef unsigned long long u64;

// Scratch (device globals; no allocations allowed)
__device__ float g_h[HH * BB];            // h transposed: g_h[k*BB + b]
__device__ float g_rh[HH * BB];           // (r * h) transposed
__device__ float g_u[HH * BB];            // u gate transposed
__device__ float g_states[BB * TT * HH];  // states row-major [B*T, H]
__device__ int   g_items[BB * TT];        // canonicalized int32 item ids
__device__ int   g_nzodd;                 // dtype-detect flag
__device__ int   g_count;                 // grid barrier counter
__device__ volatile int g_gen;            // grid barrier generation

__device__ __forceinline__ u64 fma2(u64 a, u64 b, u64 c) {
    u64 d;
    asm("fma.rn.f32x2 %0, %1, %2, %3;" : "=l"(d) : "l"(a), "l"(b), "l"(c));
    return d;
}
__device__ __forceinline__ u64 add2(u64 a, u64 b) {
    u64 d;
    asm("add.rn.f32x2 %0, %1, %2;" : "=l"(d) : "l"(a), "l"(b));
    return d;
}
__device__ __forceinline__ u64 pack2(float x, float y) {
    u64 d;
    asm("mov.b64 %0, {%1, %2};" : "=l"(d) : "f"(x), "f"(y));
    return d;
}
__device__ __forceinline__ void unpack2(u64 v, float &x, float &y) {
    asm("mov.b64 {%0, %1}, %2;" : "=f"(x), "=f"(y) : "l"(v));
}

// ---------------------------------------------------------------------------
__global__ void k_init(const float* __restrict__ h0) {
    int i = blockIdx.x * blockDim.x + threadIdx.x;
    if (i == 0) { g_nzodd = 0; g_count = 0; g_gen = 0; }
    if (i < BB * HH) {
        int b = i / HH, k = i % HH;
        g_h[k * BB + b] = h0[i];
    }
}

__global__ void k_detect(const int* __restrict__ w) {
    int i = blockIdx.x * blockDim.x + threadIdx.x;
    if (i < (BB * TT) / 2) {
        if (w[2 * i + 1] != 0) atomicOr(&g_nzodd, 1);
    }
}
__global__ void k_convert(const int* __restrict__ w) {
    int i = blockIdx.x * blockDim.x + threadIdx.x;
    if (i < BB * TT) g_items[i] = g_nzodd ? w[i] : w[2 * i];
}

// ---------------------------------------------------------------------------
// Grid barrier: atomic arrival + generation flip; spinners back off with
// __nanosleep to avoid hammering the L2 line.
__device__ __forceinline__ void gridbar() {
    __syncthreads();
    if (threadIdx.x == 0) {
        __threadfence();
        int gen = g_gen;
        if (atomicAdd(&g_count, 1) == NB - 1) {
            atomicExch(&g_count, 0);
            __threadfence();
            g_gen = gen + 1;
        } else {
            while (g_gen == gen) { __nanosleep(64); }
            __threadfence();
        }
    }
    __syncthreads();
}

// ---------------------------------------------------------------------------
// Persistent recurrence kernel. 128 blocks x 512 threads.
// Block owns: 8 col-pairs of W_ru (cols blk*16..+15) and 4 col-pairs of W_c
// (cols blk*8..+7), resident in smem for all 256 steps.
// Dynamic smem layout:
//   Wa : 8192 u64  (64 KB)  [k][cpl0..7]
//   Wb : 4096 u64  (32 KB)  [k][cpl0..3]
//   hs : 16384 f32 (64 KB)  staged h/rh chunk (512 k x 32 b)
//   red: 2048 u64  (16 KB)  cross-warp partial reduction
__global__ __launch_bounds__(512) void k_rnn(
    const float* __restrict__ Eru, const float* __restrict__ bru,
    const float* __restrict__ Ec,  const float* __restrict__ bc,
    const float* __restrict__ Wru, const float* __restrict__ Wc)
{
    extern __shared__ char smem[];
    u64*   Wa  = (u64*)smem;                     // 65536 B
    u64*   Wb  = (u64*)(smem + 65536);           // 32768 B
    float* hs  = (float*)(smem + 98304);         // 65536 B
    u64*   red = (u64*)(smem + 163840);          // 16384 B

    const int tid  = threadIdx.x;
    const int lane = tid & 31;
    const int wid  = tid >> 5;                   // 0..15
    const int blk  = blockIdx.x;

    // One-time weight load into smem (packed col-pairs)
    for (int i = tid; i < 8192; i += 512) {
        int k = i >> 3, cpl = i & 7;
        float2 w = *reinterpret_cast<const float2*>(&Wru[k * H2 + blk * 16 + 2 * cpl]);
        Wa[k * 8 + cpl] = pack2(w.x, w.y);
    }
    for (int i = tid; i < 4096; i += 512) {
        int k = i >> 2, cpl = i & 3;
        float2 w = *reinterpret_cast<const float2*>(&Wc[k * HH + blk * 8 + 2 * cpl]);
        Wb[k * 4 + cpl] = pack2(w.x, w.y);
    }

    // Output roles (guarded: only low threads own output columns)
    const int cpO   = tid >> 5;                   // warp id doubles as col-pair id
    const int col0A = blk * 16 + 2 * cpO;         // valid for tid<256 (cp 0..7)
    const int col0B = blk * 8 + 2 * cpO;          // valid for tid<128 (cp 0..3)
    float2 bA = make_float2(0.f, 0.f), bB = make_float2(0.f, 0.f);
    if (tid < 256) bA = *reinterpret_cast<const float2*>(&bru[col0A]);
    if (tid < 128) bB = *reinterpret_cast<const float2*>(&bc[col0B]);

    // Compute-split roles
    const int teamA = wid >> 3;                   // 0..1 -> cp half
    const int wkA   = wid & 7;                    // k-range (64 kl per chunk)

    __syncthreads();

    for (int t = 0; t < TT; t++) {
        // ================= Phase A: ru gates =================
        float2 eA = make_float2(0.f, 0.f);
        if (tid < 256) {
            int itA = g_items[lane * TT + t];
            eA = *reinterpret_cast<const float2*>(&Eru[itA * H2 + col0A]);
        }

        u64 a0 = 0ull, a1 = 0ull, a2 = 0ull, a3 = 0ull;
#pragma unroll
        for (int c = 0; c < 2; c++) {
            __syncthreads();
            const float4* src = (const float4*)(g_h + c * 512 * BB);
#pragma unroll
            for (int j = 0; j < 8; j++)
                ((float4*)hs)[tid + j * 512] = __ldcg(&src[tid + j * 512]);
            __syncthreads();
            const int kbase = wkA * 64;
#pragma unroll 4
            for (int kl = kbase; kl < kbase + 64; kl++) {
                float hv = hs[kl * 32 + lane];
                u64 hd = pack2(hv, hv);
                ulonglong2 w01 = *reinterpret_cast<const ulonglong2*>(
                    &Wa[(c * 512 + kl) * 8 + teamA * 4]);
                ulonglong2 w23 = *reinterpret_cast<const ulonglong2*>(
                    &Wa[(c * 512 + kl) * 8 + teamA * 4 + 2]);
                a0 = fma2(hd, w01.x, a0);
                a1 = fma2(hd, w01.y, a1);
                a2 = fma2(hd, w23.x, a2);
                a3 = fma2(hd, w23.y, a3);
            }
        }
        // partials: red[wkA][cp = teamA*4+q][lane]
        red[(wkA * 8 + teamA * 4 + 0) * 32 + lane] = a0;
        red[(wkA * 8 + teamA * 4 + 1) * 32 + lane] = a1;
        red[(wkA * 8 + teamA * 4 + 2) * 32 + lane] = a2;
        red[(wkA * 8 + teamA * 4 + 3) * 32 + lane] = a3;
        __syncthreads();
        if (tid < 256) {
            int cp = cpO;                          // 0..7
            u64 s = red[cp * 32 + lane];
#pragma unroll
            for (int w = 1; w < 8; w++)
                s = add2(s, red[(w * 8 + cp) * 32 + lane]);
            float p0, p1;
            unpack2(s, p0, p1);
            p0 += eA.x + bA.x;
            p1 += eA.y + bA.y;
            p0 = 1.0f / (1.0f + __expf(-p0));
            p1 = 1.0f / (1.0f + __expf(-p1));
            if (blk * 8 + cp < 512) {  // r gates -> r*h
                float h0 = __ldcg(&g_h[col0A * 32 + lane]);
                float h1 = __ldcg(&g_h[(col0A + 1) * 32 + lane]);
                __stcg(&g_rh[col0A * 32 + lane], p0 * h0);
                __stcg(&g_rh[(col0A + 1) * 32 + lane], p1 * h1);
            } else {                   // u gates
                __stcg(&g_u[(col0A - HH) * 32 + lane], p0);
                __stcg(&g_u[(col0A - HH + 1) * 32 + lane], p1);
            }
        }
        // Prefetch phase-B embedding gather before the barrier (independent).
        float2 eB = make_float2(0.f, 0.f);
        if (tid < 128) {
            int itB = g_items[lane * TT + t];
            eB = *reinterpret_cast<const float2*>(&Ec[itB * HH + col0B]);
        }
        gridbar();

        // ================= Phase B: candidate + h update =================
        u64 b0 = 0ull, b1 = 0ull, b2 = 0ull, b3 = 0ull;
#pragma unroll
        for (int c = 0; c < 2; c++) {
            __syncthreads();
            const float4* src = (const float4*)(g_rh + c * 512 * BB);
#pragma unroll
            for (int j = 0; j < 8; j++)
                ((float4*)hs)[tid + j * 512] = __ldcg(&src[tid + j * 512]);
            __syncthreads();
            const int kbase = wid * 32;
#pragma unroll 4
            for (int kl = kbase; kl < kbase + 32; kl++) {
                float rv = hs[kl * 32 + lane];
                u64 rd = pack2(rv, rv);
                ulonglong2 w01 = *reinterpret_cast<const ulonglong2*>(
                    &Wb[(c * 512 + kl) * 4]);
                ulonglong2 w23 = *reinterpret_cast<const ulonglong2*>(
                    &Wb[(c * 512 + kl) * 4 + 2]);
                b0 = fma2(rd, w01.x, b0);
                b1 = fma2(rd, w01.y, b1);
                b2 = fma2(rd, w23.x, b2);
                b3 = fma2(rd, w23.y, b3);
            }
        }
        // partials: red[wid][cp 0..3][lane]
        red[(wid * 4 + 0) * 32 + lane] = b0;
        red[(wid * 4 + 1) * 32 + lane] = b1;
        red[(wid * 4 + 2) * 32 + lane] = b2;
        red[(wid * 4 + 3) * 32 + lane] = b3;
        __syncthreads();
        if (tid < 128) {
            int cp = cpO;                          // 0..3
            u64 s = red[cp * 32 + lane];
#pragma unroll
            for (int w = 1; w < 16; w++)
                s = add2(s, red[(w * 4 + cp) * 32 + lane]);
            float c0, c1;
            unpack2(s, c0, c1);
            c0 = tanhf(c0 + eB.x + bB.x);
            c1 = tanhf(c1 + eB.y + bB.y);
            float u0 = __ldcg(&g_u[col0B * 32 + lane]);
            float u1 = __ldcg(&g_u[(col0B + 1) * 32 + lane]);
            float h0 = __ldcg(&g_h[col0B * 32 + lane]);
            float h1 = __ldcg(&g_h[(col0B + 1) * 32 + lane]);
            float hn0 = u0 * h0 + (1.0f - u0) * c0;
            float hn1 = u1 * h1 + (1.0f - u1) * c1;
            __stcg(&g_h[col0B * 32 + lane], hn0);
            __stcg(&g_h[(col0B + 1) * 32 + lane], hn1);
            __stcg(reinterpret_cast<float2*>(
                       &g_states[(lane * TT + t) * HH + col0B]),
                   make_float2(hn0, hn1));
        }
        gridbar();
    }
}

// ---------------------------------------------------------------------------
// Output GEMM: C[8192, V] = states[8192, H] @ W_out[H, V]
// 128m x 128n tile, 256 threads, micro 8m x 8n. A staged duplicated (a,a).
__global__ __launch_bounds__(256) void k_gemm(
    const float* __restrict__ Wo, float* __restrict__ C)
{
    const int tx = threadIdx.x & 15;   // n group: n0 = tx*8
    const int ty = threadIdx.x >> 4;   // m group: m0 = ty*8
    const int mt = blockIdx.x * 128;
    const int nt = blockIdx.y * 128;

    __shared__ u64   Asd[16][128];     // 16 KB, (a,a) dup [k][m]
    __shared__ float Bs[16][128];      //  8 KB

    u64 acc[8][4];
#pragma unroll
    for (int i = 0; i < 8; i++)
#pragma unroll
        for (int j = 0; j < 4; j++) acc[i][j] = 0ull;

    const int am  = threadIdx.x >> 1;        // 0..127
    const int ak4 = (threadIdx.x & 1) * 8;   // 0 or 8

    for (int k0 = 0; k0 < HH; k0 += 16) {
        float4 av0 = *reinterpret_cast<const float4*>(
            &g_states[(mt + am) * HH + k0 + ak4]);
        float4 av1 = *reinterpret_cast<const float4*>(
            &g_states[(mt + am) * HH + k0 + ak4 + 4]);
        float bv[8];
#pragma unroll
        for (int j = 0; j < 8; j++) {
            int idx = threadIdx.x + j * 256;      // 0..2047
            int bk = idx >> 7, bn = idx & 127;
            int ncol = nt + bn;
            bv[j] = (ncol < VV) ? Wo[(k0 + bk) * VV + ncol] : 0.0f;
        }
        __syncthreads();
        Asd[ak4 + 0][am] = pack2(av0.x, av0.x);
        Asd[ak4 + 1][am] = pack2(av0.y, av0.y);
        Asd[ak4 + 2][am] = pack2(av0.z, av0.z);
        Asd[ak4 + 3][am] = pack2(av0.w, av0.w);
        Asd[ak4 + 4][am] = pack2(av1.x, av1.x);
        Asd[ak4 + 5][am] = pack2(av1.y, av1.y);
        Asd[ak4 + 6][am] = pack2(av1.z, av1.z);
        Asd[ak4 + 7][am] = pack2(av1.w, av1.w);
#pragma unroll
        for (int j = 0; j < 8; j++) {
            int idx = threadIdx.x + j * 256;
            Bs[idx >> 7][idx & 127] = bv[j];
        }
        __syncthreads();
#pragma unroll
        for (int k = 0; k < 16; k++) {
            ulonglong2 a01 = *reinterpret_cast<const ulonglong2*>(&Asd[k][ty * 8]);
            ulonglong2 a23 = *reinterpret_cast<const ulonglong2*>(&Asd[k][ty * 8 + 2]);
            ulonglong2 a45 = *reinterpret_cast<const ulonglong2*>(&Asd[k][ty * 8 + 4]);
            ulonglong2 a67 = *reinterpret_cast<const ulonglong2*>(&Asd[k][ty * 8 + 6]);
            ulonglong2 bl = *reinterpret_cast<const ulonglong2*>(&Bs[k][tx * 8]);
            ulonglong2 bh = *reinterpret_cast<const ulonglong2*>(&Bs[k][tx * 8 + 4]);
            u64 a[8] = {a01.x, a01.y, a23.x, a23.y, a45.x, a45.y, a67.x, a67.y};
#pragma unroll
            for (int i = 0; i < 8; i++) {
                acc[i][0] = fma2(a[i], bl.x, acc[i][0]);
                acc[i][1] = fma2(a[i], bl.y, acc[i][1]);
                acc[i][2] = fma2(a[i], bh.x, acc[i][2]);
                acc[i][3] = fma2(a[i], bh.y, acc[i][3]);
            }
        }
    }

    // Epilogue (scalar stores; V=10001 rows are 16B-misaligned)
#pragma unroll
    for (int i = 0; i < 8; i++) {
        int m = mt + ty * 8 + i;
        float* row = &C[m * VV];
#pragma unroll
        for (int j = 0; j < 4; j++) {
            float c0, c1;
            unpack2(acc[i][j], c0, c1);
            int n = nt + tx * 8 + j * 2;
            if (n < VV)     row[n]     = c0;
            if (n + 1 < VV) row[n + 1] = c1;
        }
    }
}

// ---------------------------------------------------------------------------
// h_final: g_h [H,B] -> out [B,H]
__global__ void k_hfinal(float* __restrict__ out) {
    int i = blockIdx.x * blockDim.x + threadIdx.x;
    if (i < BB * HH) {
        int b = i / HH, k = i % HH;
        out[i] = g_h[k * BB + b];
    }
}

// ---------------------------------------------------------------------------
extern "C" void kernel_launch(void* const* d_in, const int* in_sizes, int n_in,
                              void* d_out, int out_size)
{
    const int*   items_raw = (const int*)d_in[0];
    const float* h0   = (const float*)d_in[1];
    const float* E_ru = (const float*)d_in[2];
    const float* W_ru = (const float*)d_in[3];
    const float* b_ru = (const float*)d_in[4];
    const float* E_c  = (const float*)d_in[5];
    const float* W_c  = (const float*)d_in[6];
    const float* b_c  = (const float*)d_in[7];
    const float* W_out = (const float*)d_in[8];

    float* out = (float*)d_out;
    float* logits = out + BB * HH;

    cudaFuncSetAttribute(k_rnn, cudaFuncAttributeMaxDynamicSharedMemorySize,
                         180224);

    k_init<<<(BB * HH + 255) / 256, 256>>>(h0);
    k_detect<<<(BB * TT / 2 + 255) / 256, 256>>>(items_raw);
    k_convert<<<(BB * TT + 255) / 256, 256>>>(items_raw);

    k_rnn<<<NB, 512, 180224>>>(E_ru, b_ru, E_c, b_c, W_ru, W_c);

    dim3 ggrid((BB * TT) / 128, (VV + 127) / 128);
    k_gemm<<<ggrid, 256>>>(W_out, logits);

    k_hfinal<<<(BB * HH + 255) / 256, 256>>>(out);
}